// round 3
// baseline (speedup 1.0000x reference)
#include <cuda_runtime.h>

#define S  512
#define S2 (S*S)
#define NBATCH 32
#define NBLK_TOTAL 8192u

// Global accumulators (zero at load; finalize resets them each run)
__device__ double g_acc[2] = {0.0, 0.0};         // [0]=sum|cont|, [1]=sum|pois|
__device__ double g_bc4[NBATCH * 4] = {0.0};     // per-batch per-edge signed sums
__device__ unsigned int g_count = 0u;

__global__ __launch_bounds__(256) void pil_kernel(const float* __restrict__ gen,
                                                  const float* __restrict__ pn,
                                                  float* __restrict__ out) {
    // halo tile: global rows i0-2..i0+32, cols j0-2..j0+32 (35x35), stride 36
    __shared__ float su[35][36], sv[35][36], sp[35][36], sq[35][36];
    __shared__ float redC[8], redP[8];
    __shared__ double dred[8];
    __shared__ unsigned int s_ticket;

    const int bx = blockIdx.x, by = blockIdx.y, b = blockIdx.z;
    const int i0 = 1 + by * 32;
    const int j0 = 1 + bx * 32;
    const int tid = threadIdx.x;
    const int tx = tid & 31, ty = tid >> 5;

    const float* u = gen + (size_t)b * 3 * S2;
    const float* v = u + S2;
    const float* p = v + S2;
    const float* q = pn + (size_t)b * S2;

    // ---- load halo tiles (clamped; clamped cells only feed guarded-out paths) ----
    for (int idx = tid; idx < 35 * 35; idx += 256) {
        int r = idx / 35, c = idx - r * 35;
        int gy = i0 - 2 + r; gy = max(0, min(S - 1, gy));
        int gx = j0 - 2 + c; gx = max(0, min(S - 1, gx));
        int g = gy * S + gx;
        su[r][c] = u[g];
        sv[r][c] = v[g];
        sp[r][c] = p[g];
        sq[r][c] = q[g];
    }
    __syncthreads();

    const int lc  = tx + 2;          // local col of j
    const int j   = j0 + tx;
    const bool ujv = (j <= 509);     // u_new validity (j>=1 always)
    const bool jv  = (j <= 510);     // residual col validity
    const int lr0 = ty * 4 + 2;      // local row of first output row
    const int ir0 = i0 + ty * 4;     // global first output row

    float accC = 0.0f, accP = 0.0f;

    // ---- rolled register state ----
    float uc  = su[lr0][lc];
    float uN  = su[lr0 - 1][lc];
    float vcC = sv[lr0][lc];
    float vcN = sv[lr0 - 1][lc];
    float vNN = sv[lr0 - 2][lc];
    float pC  = sp[lr0][lc];
    float pN  = sp[lr0 - 1][lc];
    float qC  = sq[lr0][lc];
    float qN  = sq[lr0 - 1][lc];

    // fn_prev = u-flux between rows (ir0-1, ir0); gn_prev = v-flux between (ir0-2, ir0-1)
    float fn_prev = 0.5f * (vcN + sv[lr0 - 1][lc + 1]) * (0.5f * (uN + uc)) - (uc - uN);
    float ga0 = 0.5f * (vNN + vcN);
    float gn_prev = ga0 * ga0 - (vcN - vNN);

    // vn_prev = v_new at global row ir0-1
    float vn_prev;
    {
        float vem = sv[lr0 - 1][lc + 1];
        float ge1 = 0.5f * (uN + uc) * (0.5f * (vcN + vem)) - (vem - vcN);
        float ge0 = __shfl_up_sync(0xFFFFFFFFu, ge1, 1);
        if (tx == 0) {
            float vw0 = sv[lr0 - 1][1];
            ge0 = 0.5f * (su[lr0 - 1][1] + su[lr0][1]) * (0.5f * (vw0 + vcN)) - (vcN - vw0);
        }
        float a1 = 0.5f * (vcN + vcC);
        float gn1 = a1 * a1 - (vcC - vcN);
        float dvdt = (-(ge1 - ge0) - (gn1 - gn_prev) - (pC - pN)) * 100.0f;
        int im = ir0 - 1;
        vn_prev = (im >= 1 && im <= 509) ? vcN + dvdt * 0.001f : vcN;
        gn_prev = gn1;
    }

    #pragma unroll
    for (int k = 0; k < 4; k++) {
        const int lr = lr0 + k;
        const int i  = ir0 + k;
        float uS = su[lr + 1][lc];
        float uw = su[lr][lc - 1];
        float ue = su[lr][lc + 1];
        float vS = sv[lr + 1][lc];
        float ve = sv[lr][lc + 1];
        float pS = sp[lr + 1][lc];
        float pE = sp[lr][lc + 1];
        float pW = sp[lr][lc - 1];
        float qS = sq[lr + 1][lc];
        float qE = sq[lr][lc + 1];
        float qW = sq[lr][lc - 1];

        // ---- u_new(i, j) ----
        float ax1 = 0.5f * (uc + ue); float fe1 = ax1 * ax1 - (ue - uc);
        float ax0 = 0.5f * (uw + uc); float fe0 = ax0 * ax0 - (uc - uw);
        float fn1 = 0.5f * (vcC + ve) * (0.5f * (uc + uS)) - (uS - uc);
        float dudt = (-(fe1 - fe0) - (fn1 - fn_prev) - (pE - pC)) * 100.0f;
        float un = (ujv && i <= 510) ? uc + dudt * 0.001f : uc;
        float un0 = __shfl_up_sync(0xFFFFFFFFu, un, 1);

        // ---- v_new(i, j) ----
        float ge1 = 0.5f * (uc + uS) * (0.5f * (vcC + ve)) - (ve - vcC);
        float ge0 = __shfl_up_sync(0xFFFFFFFFu, ge1, 1);

        if (tx == 0) {
            // extra column j0-1 for un0, and local ge0 (no left neighbor lane)
            float uc0 = su[lr][1], uw0 = su[lr][0];
            float us0 = su[lr + 1][1], un_0 = su[lr - 1][1];
            float vw0 = sv[lr][1];
            float axa = 0.5f * (uc0 + uc);  float fea = axa * axa - (uc - uc0);
            float axb = 0.5f * (uw0 + uc0); float feb = axb * axb - (uc0 - uw0);
            float fva1 = 0.5f * (vw0 + vcC) * (0.5f * (uc0 + us0)) - (us0 - uc0);
            float fva0 = 0.5f * (sv[lr - 1][1] + vcN) * (0.5f * (un_0 + uc0)) - (uc0 - un_0);
            float dudt0 = (-(fea - feb) - (fva1 - fva0) - (pC - sp[lr][1])) * 100.0f;
            un0 = (bx > 0 && i <= 510) ? uc0 + dudt0 * 0.001f : uc0;
            ge0 = 0.5f * (uc0 + us0) * (0.5f * (vw0 + vcC)) - (vcC - vw0);
        }

        float gna = 0.5f * (vcC + vS); float gn1 = gna * gna - (vS - vcC);
        float dvdt = (-(ge1 - ge0) - (gn1 - gn_prev) - (pS - pC)) * 100.0f;
        float vn = (i <= 509) ? vcC + dvdt * 0.001f : vcC;

        // ---- residuals ----
        if (jv && i <= 510) {
            float cont = (uc - uw + vcC - vcN) * 100.0f;
            float bconv = ((un - un0) + (vn - vn_prev)) * 100000.0f;
            float lap = 4.0f * (qC - pC) - (qE - pE) - (qW - pW) - (qS - pS) - (qN - pN);
            accC += fabsf(cont);
            accP += fabsf(lap * 10000.0f + bconv);
        }

        // ---- roll ----
        fn_prev = fn1; gn_prev = gn1; vn_prev = vn;
        uc = uS; vcN = vcC; vcC = vS;
        pN = pC; pC = pS; qN = qC; qC = qS;
    }

    // ---- boundary-condition edge sums (edge blocks only, from loaded smem) ----
    {
        float es = 0.0f; int eidx = -1;
        if (tid < 32) {
            int jj = j0 + tid, lcc = tid + 2;
            if (by == 0) {
                eidx = 0;
                if (jj <= 509) es += su[1][lcc] + su[2][lcc];
                if (jj <= 510) es += sv[1][lcc] + sp[1][lcc];
            } else if (by == 15) {
                eidx = 1;
                if (jj <= 509) es += 2.0f - (su[31][lcc] + su[32][lcc]);
                if (jj <= 510) es += sv[32][lcc] + sp[32][lcc];
            }
        } else if (tid < 64) {
            int lane = tid - 32;
            int ii = i0 + lane, lrr = lane + 2;
            if (bx == 0) {
                eidx = 2;
                if (ii <= 509) es += sv[lrr][1] + sv[lrr][2];
                if (ii <= 510) es += su[lrr][1] + sp[lrr][1];
            } else if (bx == 15) {
                eidx = 3;
                if (ii <= 509) es += sv[lrr][32] + sv[lrr][31];
                if (ii <= 510) es += su[lrr][32] + sp[lrr][32];
            }
        }
        if (eidx >= 0) {
            #pragma unroll
            for (int off = 16; off > 0; off >>= 1)
                es += __shfl_down_sync(0xFFFFFFFFu, es, off);
            if ((tid & 31) == 0)
                atomicAdd(&g_bc4[b * 4 + eidx], (double)es);
        }
    }

    // ---- block reduction of residual sums ----
    #pragma unroll
    for (int off = 16; off > 0; off >>= 1) {
        accC += __shfl_down_sync(0xFFFFFFFFu, accC, off);
        accP += __shfl_down_sync(0xFFFFFFFFu, accP, off);
    }
    if ((tid & 31) == 0) { redC[ty] = accC; redP[ty] = accP; }
    __syncthreads();
    if (ty == 0) {
        float rc = (tx < 8) ? redC[tx] : 0.0f;
        float rp = (tx < 8) ? redP[tx] : 0.0f;
        #pragma unroll
        for (int off = 4; off > 0; off >>= 1) {
            rc += __shfl_down_sync(0xFFFFFFFFu, rc, off);
            rp += __shfl_down_sync(0xFFFFFFFFu, rp, off);
        }
        if (tx == 0) {
            atomicAdd(&g_acc[0], (double)rc);
            atomicAdd(&g_acc[1], (double)rp);
        }
    }

    // ---- last-block finalize ----
    __threadfence();
    if (tid == 0) s_ticket = atomicAdd(&g_count, 1u);
    __syncthreads();
    if (s_ticket == NBLK_TOTAL - 1u) {
        double mybc = 0.0;
        if (tid < NBATCH * 4)
            mybc = fabs(atomicAdd(&g_bc4[tid], 0.0));
        #pragma unroll
        for (int off = 16; off > 0; off >>= 1)
            mybc += __shfl_down_sync(0xFFFFFFFFu, mybc, off);
        if ((tid & 31) == 0) dred[ty] = mybc;
        __syncthreads();
        if (tid == 0) {
            double bc = 0.0;
            #pragma unroll
            for (int kk = 0; kk < 8; kk++) bc += dred[kk];
            double C = atomicAdd(&g_acc[0], 0.0);
            double P = atomicAdd(&g_acc[1], 0.0);
            double denom = 32.0 * 510.0 * 510.0;
            out[0] = (float)(0.4 * (C / denom) + 0.2 * bc + (1.0 - 0.4 - 0.2) * (P / denom));
            g_acc[0] = 0.0; g_acc[1] = 0.0;
        }
        if (tid < NBATCH * 4) g_bc4[tid] = 0.0;
        __threadfence();
        __syncthreads();
        if (tid == 0) g_count = 0u;
    }
}

extern "C" void kernel_launch(void* const* d_in, const int* in_sizes, int n_in,
                              void* d_out, int out_size) {
    const float* gen = (const float*)d_in[0];
    const float* pn  = (const float*)d_in[1];
    float* out = (float*)d_out;
    dim3 grid(16, 16, NBATCH);   // 16 x 16 x 32 = 8192 blocks
    pil_kernel<<<grid, 256>>>(gen, pn, out);
}

// round 4
// speedup vs baseline: 1.1714x; 1.1714x over previous
#include <cuda_runtime.h>

#define S  512
#define S2 (S*S)
#define NBATCH 32
#define NBLK_TOTAL 8192u

// Global accumulators (zero at load; finalize resets them each run)
__device__ double g_acc[2] = {0.0, 0.0};         // [0]=sum|cont|, [1]=sum|pois|
__device__ double g_bc4[NBATCH * 4] = {0.0};     // per-batch per-edge signed sums
__device__ unsigned int g_count = 0u;

// Per-thread 4-row strip. INT = fully interior block (no guards needed).
template<bool INT>
__device__ __forceinline__ void tile_compute(
    const float (*__restrict__ su)[36], const float (*__restrict__ sv)[36],
    const float (*__restrict__ sp)[36], const float (*__restrict__ sd)[36],
    int tx, int ty, int i0, int j0, float& accC, float& accP)
{
    const int lc  = tx + 2;
    const int lr0 = ty * 4 + 2;
    const int ir0 = i0 + ty * 4;
    const int j   = j0 + tx;

    // ---- rolled field state at row lr0 ----
    float u_m2 = su[lr0][lc-2], u_m1 = su[lr0][lc-1], u_0 = su[lr0][lc], u_p1 = su[lr0][lc+1];
    float v_m1 = sv[lr0][lc-1], v_0 = sv[lr0][lc], v_p1 = sv[lr0][lc+1];
    float vN_0 = sv[lr0-1][lc];
    float p_m1 = sp[lr0][lc-1], p_0 = sp[lr0][lc], p_p1 = sp[lr0][lc+1];
    float d_m1 = sd[lr0][lc-1], d_0 = sd[lr0][lc], d_p1 = sd[lr0][lc+1];
    float d_N  = sd[lr0-1][lc];

    // ---- flux init between rows ir0-1 and ir0 ----
    float uN_0 = su[lr0-1][lc], uN_m1 = su[lr0-1][lc-1];
    float vN_m1 = sv[lr0-1][lc-1], vN_p1 = sv[lr0-1][lc+1];
    float prodN  = (0.5f*(vN_0 + vN_p1)) * (0.5f*(uN_0 + u_0));
    float prodNm = (0.5f*(vN_m1 + vN_0)) * (0.5f*(uN_m1 + u_m1));
    float fn_prev   = prodN  - (u_0  - uN_0);
    float fn_prev_m = prodNm - (u_m1 - uN_m1);
    float vNN_0 = sv[lr0-2][lc];
    float ga = 0.5f*(vNN_0 + vN_0);
    float gn_prev = ga*ga - (vN_0 - vNN_0);
    // vn_prev = v_new(ir0-1, j)
    float geN1 = prodN  - (vN_p1 - vN_0);
    float geN0 = prodNm - (vN_0  - vN_m1);
    float gaa  = 0.5f*(vN_0 + v_0);
    float gnN1 = gaa*gaa - (v_0 - vN_0);
    float pN_0 = sp[lr0-1][lc];
    float dvdtN = (-(geN1 - geN0) - (gnN1 - gn_prev) - (p_0 - pN_0)) * 100.0f;
    float vn_prev = vN_0 + dvdtN * 0.001f;
    if (!INT) { if (ir0 - 1 < 1) vn_prev = vN_0; }
    gn_prev = gnN1;

    #pragma unroll
    for (int k = 0; k < 4; k++) {
        const int lr = lr0 + k;
        const int i  = ir0 + k;
        // next-row loads (13 LDS)
        float uS_m2 = su[lr+1][lc-2], uS_m1 = su[lr+1][lc-1], uS_0 = su[lr+1][lc], uS_p1 = su[lr+1][lc+1];
        float vS_m1 = sv[lr+1][lc-1], vS_0 = sv[lr+1][lc], vS_p1 = sv[lr+1][lc+1];
        float pS_m1 = sp[lr+1][lc-1], pS_0 = sp[lr+1][lc], pS_p1 = sp[lr+1][lc+1];
        float dS_m1 = sd[lr+1][lc-1], dS_0 = sd[lr+1][lc], dS_p1 = sd[lr+1][lc+1];

        // horizontal u fluxes (row lr)
        float ea = 0.5f*(u_m2 + u_m1); float fe0m = ea*ea - (u_m1 - u_m2);
        float eb = 0.5f*(u_m1 + u_0);  float fe0  = eb*eb - (u_0  - u_m1);
        float ec = 0.5f*(u_0  + u_p1); float fe1  = ec*ec - (u_p1 - u_0);
        // shared cross products (u-y flux and v-x flux share them)
        float prod  = (0.5f*(v_0  + v_p1)) * (0.5f*(u_0  + uS_0));
        float prodm = (0.5f*(v_m1 + v_0))  * (0.5f*(u_m1 + uS_m1));
        float fn1  = prod  - (uS_0  - u_0);
        float fn1m = prodm - (uS_m1 - u_m1);
        float ge1  = prod  - (v_p1 - v_0);
        float ge0  = prodm - (v_0  - v_m1);
        float gna = 0.5f*(v_0 + vS_0); float gn1 = gna*gna - (vS_0 - v_0);

        float dudt  = (-(fe1 - fe0)  - (fn1  - fn_prev)   - (p_p1 - p_0)) * 100.0f;
        float dudtm = (-(fe0 - fe0m) - (fn1m - fn_prev_m) - (p_0 - p_m1)) * 100.0f;
        float dvdt  = (-(ge1 - ge0)  - (gn1  - gn_prev)   - (pS_0 - p_0)) * 100.0f;

        float un  = u_0  + dudt  * 0.001f;
        float unm = u_m1 + dudtm * 0.001f;
        float vn  = v_0  + dvdt  * 0.001f;
        if (!INT) {
            if (j > 509 || i > 510)     un  = u_0;    // u_new identity outside [1,510]x[1,509]
            if (j - 1 < 1 || i > 510)   unm = u_m1;
            if (i > 509)                vn  = v_0;    // v_new identity outside [1,509]x[1,510]
        }

        float cont  = (u_0 - u_m1 + v_0 - vN_0) * 100.0f;
        float bconv = ((un - unm) + (vn - vn_prev)) * 100000.0f;
        float lap   = 4.0f*d_0 - d_p1 - d_m1 - dS_0 - d_N;
        float pois  = fmaf(lap, 10000.0f, bconv);
        if (INT || (i <= 510 && j <= 510)) {
            accC += fabsf(cont);
            accP += fabsf(pois);
        }

        // roll
        fn_prev = fn1; fn_prev_m = fn1m; gn_prev = gn1; vn_prev = vn;
        u_m2 = uS_m2; u_m1 = uS_m1; u_0 = uS_0; u_p1 = uS_p1;
        vN_0 = v_0;   v_m1 = vS_m1; v_0 = vS_0; v_p1 = vS_p1;
        p_m1 = pS_m1; p_0 = pS_0;   p_p1 = pS_p1;
        d_N  = d_0;   d_m1 = dS_m1; d_0 = dS_0; d_p1 = dS_p1;
    }
}

__global__ __launch_bounds__(256) void pil_kernel(const float* __restrict__ gen,
                                                  const float* __restrict__ pn,
                                                  float* __restrict__ out) {
    // halo tile: global rows i0-2..i0+32, cols j0-2..j0+32 (35x35), stride 36
    __shared__ float su[35][36], sv[35][36], sp[35][36], sd[35][36];
    __shared__ float redC[8], redP[8];
    __shared__ double dred[8];
    __shared__ unsigned int s_ticket;

    const int bx = blockIdx.x, by = blockIdx.y, b = blockIdx.z;
    const int i0 = 1 + by * 32;
    const int j0 = 1 + bx * 32;
    const int tid = threadIdx.x;
    const int tx = tid & 31, ty = tid >> 5;

    const float* u = gen + (size_t)b * 3 * S2;
    const float* v = u + S2;
    const float* p = v + S2;
    const float* q = pn + (size_t)b * S2;

    // ---- load halo tiles (clamped; clamped cells only feed guarded-out paths) ----
    for (int idx = tid; idx < 35 * 35; idx += 256) {
        int r = idx / 35, c = idx - r * 35;
        int gy = i0 - 2 + r; gy = max(0, min(S - 1, gy));
        int gx = j0 - 2 + c; gx = max(0, min(S - 1, gx));
        int g = gy * S + gx;
        su[r][c] = u[g];
        sv[r][c] = v[g];
        float pv = p[g];
        sp[r][c] = pv;
        sd[r][c] = q[g] - pv;     // p' = p_next - p
    }
    __syncthreads();

    float accC = 0.0f, accP = 0.0f;
    const bool interior = (bx >= 1) && (bx <= 14) && (by >= 1) && (by <= 14);
    if (interior) {
        tile_compute<true >(su, sv, sp, sd, tx, ty, i0, j0, accC, accP);
    } else {
        tile_compute<false>(su, sv, sp, sd, tx, ty, i0, j0, accC, accP);

        // ---- boundary-condition edge sums (edge blocks only, from loaded smem) ----
        float es = 0.0f; int eidx = -1;
        if (tid < 32) {
            int jj = j0 + tid, lcc = tid + 2;
            if (by == 0) {
                eidx = 0;
                if (jj <= 509) es += su[1][lcc] + su[2][lcc];
                if (jj <= 510) es += sv[1][lcc] + sp[1][lcc];
            } else if (by == 15) {
                eidx = 1;
                if (jj <= 509) es += 2.0f - (su[31][lcc] + su[32][lcc]);
                if (jj <= 510) es += sv[32][lcc] + sp[32][lcc];
            }
        } else if (tid < 64) {
            int lane = tid - 32;
            int ii = i0 + lane, lrr = lane + 2;
            if (bx == 0) {
                eidx = 2;
                if (ii <= 509) es += sv[lrr][1] + sv[lrr][2];
                if (ii <= 510) es += su[lrr][1] + sp[lrr][1];
            } else if (bx == 15) {
                eidx = 3;
                if (ii <= 509) es += sv[lrr][32] + sv[lrr][31];
                if (ii <= 510) es += su[lrr][32] + sp[lrr][32];
            }
        }
        if (eidx >= 0) {
            #pragma unroll
            for (int off = 16; off > 0; off >>= 1)
                es += __shfl_down_sync(0xFFFFFFFFu, es, off);
            if ((tid & 31) == 0)
                atomicAdd(&g_bc4[b * 4 + eidx], (double)es);
        }
    }

    // ---- block reduction of residual sums ----
    #pragma unroll
    for (int off = 16; off > 0; off >>= 1) {
        accC += __shfl_down_sync(0xFFFFFFFFu, accC, off);
        accP += __shfl_down_sync(0xFFFFFFFFu, accP, off);
    }
    if ((tid & 31) == 0) { redC[ty] = accC; redP[ty] = accP; }
    __syncthreads();
    if (ty == 0) {
        float rc = (tx < 8) ? redC[tx] : 0.0f;
        float rp = (tx < 8) ? redP[tx] : 0.0f;
        #pragma unroll
        for (int off = 4; off > 0; off >>= 1) {
            rc += __shfl_down_sync(0xFFFFFFFFu, rc, off);
            rp += __shfl_down_sync(0xFFFFFFFFu, rp, off);
        }
        if (tx == 0) {
            atomicAdd(&g_acc[0], (double)rc);
            atomicAdd(&g_acc[1], (double)rp);
        }
    }

    // ---- last-block finalize ----
    __threadfence();
    if (tid == 0) s_ticket = atomicAdd(&g_count, 1u);
    __syncthreads();
    if (s_ticket == NBLK_TOTAL - 1u) {
        double mybc = 0.0;
        if (tid < NBATCH * 4)
            mybc = fabs(atomicAdd(&g_bc4[tid], 0.0));
        #pragma unroll
        for (int off = 16; off > 0; off >>= 1)
            mybc += __shfl_down_sync(0xFFFFFFFFu, mybc, off);
        if ((tid & 31) == 0) dred[ty] = mybc;
        __syncthreads();
        if (tid == 0) {
            double bc = 0.0;
            #pragma unroll
            for (int kk = 0; kk < 8; kk++) bc += dred[kk];
            double C = atomicAdd(&g_acc[0], 0.0);
            double P = atomicAdd(&g_acc[1], 0.0);
            double denom = 32.0 * 510.0 * 510.0;
            out[0] = (float)(0.4 * (C / denom) + 0.2 * bc + (1.0 - 0.4 - 0.2) * (P / denom));
            g_acc[0] = 0.0; g_acc[1] = 0.0;
        }
        if (tid < NBATCH * 4) g_bc4[tid] = 0.0;
        __threadfence();
        __syncthreads();
        if (tid == 0) g_count = 0u;
    }
}

extern "C" void kernel_launch(void* const* d_in, const int* in_sizes, int n_in,
                              void* d_out, int out_size) {
    const float* gen = (const float*)d_in[0];
    const float* pn  = (const float*)d_in[1];
    float* out = (float*)d_out;
    dim3 grid(16, 16, NBATCH);   // 16 x 16 x 32 = 8192 blocks
    pil_kernel<<<grid, 256>>>(gen, pn, out);
}

// round 5
// speedup vs baseline: 1.1967x; 1.0215x over previous
#include <cuda_runtime.h>

#define S  512
#define S2 (S*S)
#define NBATCH 32
#define NBLK_TOTAL 4096u
#define TROWS 67            // halo rows: 64 + 3

// Global accumulators (zero at load; finalize resets them each run)
__device__ double g_acc[2] = {0.0, 0.0};         // [0]=sum|cont|, [1]=sum|pois|
__device__ double g_bc4[NBATCH * 4] = {0.0};     // per-batch per-edge signed sums
__device__ unsigned int g_count = 0u;

// Per-thread 8-row strip. INT = fully interior block (no guards).
template<bool INT>
__device__ __forceinline__ void tile_compute(
    const float (*__restrict__ su)[36], const float (*__restrict__ sv)[36],
    const float (*__restrict__ sp)[36], const float (*__restrict__ sd)[36],
    int tx, int ty, int i0, int j0, float& accC, float& accP)
{
    const int lc  = tx + 2;
    const int lr0 = ty * 8 + 2;
    const int ir0 = i0 + ty * 8;
    const int j   = j0 + tx;

    // ---- rolled field state at row lr0 ----
    float u_m2 = su[lr0][lc-2], u_m1 = su[lr0][lc-1], u_0 = su[lr0][lc], u_p1 = su[lr0][lc+1];
    float v_m1 = sv[lr0][lc-1], v_0 = sv[lr0][lc], v_p1 = sv[lr0][lc+1];
    float vN_0 = sv[lr0-1][lc];
    float p_m1 = sp[lr0][lc-1], p_0 = sp[lr0][lc], p_p1 = sp[lr0][lc+1];
    float d_m1 = sd[lr0][lc-1], d_0 = sd[lr0][lc], d_p1 = sd[lr0][lc+1];
    float d_N  = sd[lr0-1][lc];

    // ---- flux init between rows ir0-1 and ir0 ----
    float uN_0 = su[lr0-1][lc], uN_m1 = su[lr0-1][lc-1];
    float vN_m1 = sv[lr0-1][lc-1], vN_p1 = sv[lr0-1][lc+1];
    float prodN  = (0.5f*(vN_0 + vN_p1)) * (0.5f*(uN_0 + u_0));
    float prodNm = (0.5f*(vN_m1 + vN_0)) * (0.5f*(uN_m1 + u_m1));
    float fn_prev   = prodN  - (u_0  - uN_0);
    float fn_prev_m = prodNm - (u_m1 - uN_m1);
    float vNN_0 = sv[lr0-2][lc];
    float ga = 0.5f*(vNN_0 + vN_0);
    float gn_prev = ga*ga - (vN_0 - vNN_0);
    // vn_prev = v_new(ir0-1, j)
    float geN1 = prodN  - (vN_p1 - vN_0);
    float geN0 = prodNm - (vN_0  - vN_m1);
    float gaa  = 0.5f*(vN_0 + v_0);
    float gnN1 = gaa*gaa - (v_0 - vN_0);
    float pN_0 = sp[lr0-1][lc];
    float dvdtN = (-(geN1 - geN0) - (gnN1 - gn_prev) - (p_0 - pN_0)) * 100.0f;
    float vn_prev = vN_0 + dvdtN * 0.001f;
    if (!INT) { if (ir0 - 1 < 1) vn_prev = vN_0; }
    gn_prev = gnN1;

    #pragma unroll
    for (int k = 0; k < 8; k++) {
        const int lr = lr0 + k;
        const int i  = ir0 + k;
        // next-row loads (13 LDS)
        float uS_m2 = su[lr+1][lc-2], uS_m1 = su[lr+1][lc-1], uS_0 = su[lr+1][lc], uS_p1 = su[lr+1][lc+1];
        float vS_m1 = sv[lr+1][lc-1], vS_0 = sv[lr+1][lc], vS_p1 = sv[lr+1][lc+1];
        float pS_m1 = sp[lr+1][lc-1], pS_0 = sp[lr+1][lc], pS_p1 = sp[lr+1][lc+1];
        float dS_m1 = sd[lr+1][lc-1], dS_0 = sd[lr+1][lc], dS_p1 = sd[lr+1][lc+1];

        // horizontal u fluxes (row lr)
        float ea = 0.5f*(u_m2 + u_m1); float fe0m = ea*ea - (u_m1 - u_m2);
        float eb = 0.5f*(u_m1 + u_0);  float fe0  = eb*eb - (u_0  - u_m1);
        float ec = 0.5f*(u_0  + u_p1); float fe1  = ec*ec - (u_p1 - u_0);
        // shared cross products (u-y flux and v-x flux share them)
        float prod  = (0.5f*(v_0  + v_p1)) * (0.5f*(u_0  + uS_0));
        float prodm = (0.5f*(v_m1 + v_0))  * (0.5f*(u_m1 + uS_m1));
        float fn1  = prod  - (uS_0  - u_0);
        float fn1m = prodm - (uS_m1 - u_m1);
        float ge1  = prod  - (v_p1 - v_0);
        float ge0  = prodm - (v_0  - v_m1);
        float gna = 0.5f*(v_0 + vS_0); float gn1 = gna*gna - (vS_0 - v_0);

        float dudt  = (-(fe1 - fe0)  - (fn1  - fn_prev)   - (p_p1 - p_0)) * 100.0f;
        float dudtm = (-(fe0 - fe0m) - (fn1m - fn_prev_m) - (p_0 - p_m1)) * 100.0f;
        float dvdt  = (-(ge1 - ge0)  - (gn1  - gn_prev)   - (pS_0 - p_0)) * 100.0f;

        float un  = u_0  + dudt  * 0.001f;
        float unm = u_m1 + dudtm * 0.001f;
        float vn  = v_0  + dvdt  * 0.001f;
        if (!INT) {
            if (j > 509 || i > 510)     un  = u_0;
            if (j - 1 < 1 || i > 510)   unm = u_m1;
            if (i > 509)                vn  = v_0;
        }

        float cont  = (u_0 - u_m1 + v_0 - vN_0) * 100.0f;
        float bconv = ((un - unm) + (vn - vn_prev)) * 100000.0f;
        float lap   = 4.0f*d_0 - d_p1 - d_m1 - dS_0 - d_N;
        float pois  = fmaf(lap, 10000.0f, bconv);
        if (INT || (i <= 510 && j <= 510)) {
            accC += fabsf(cont);
            accP += fabsf(pois);
        }

        // roll
        fn_prev = fn1; fn_prev_m = fn1m; gn_prev = gn1; vn_prev = vn;
        u_m2 = uS_m2; u_m1 = uS_m1; u_0 = uS_0; u_p1 = uS_p1;
        vN_0 = v_0;   v_m1 = vS_m1; v_0 = vS_0; v_p1 = vS_p1;
        p_m1 = pS_m1; p_0 = pS_0;   p_p1 = pS_p1;
        d_N  = d_0;   d_m1 = dS_m1; d_0 = dS_0; d_p1 = dS_p1;
    }
}

__global__ __launch_bounds__(256) void pil_kernel(const float* __restrict__ gen,
                                                  const float* __restrict__ pn,
                                                  float* __restrict__ out) {
    // halo tile: global rows i0-2..i0+64, cols j0-2..j0+32 (67x35), stride 36
    __shared__ float su[TROWS][36], sv[TROWS][36], sp[TROWS][36], sd[TROWS][36];
    __shared__ float redC[8], redP[8];
    __shared__ double dred[8];
    __shared__ unsigned int s_ticket;

    const int bx = blockIdx.x, by = blockIdx.y, b = blockIdx.z;
    const int i0 = 1 + by * 64;
    const int j0 = 1 + bx * 32;
    const int tid = threadIdx.x;
    const int tx = tid & 31, ty = tid >> 5;   // ty = warp id, 0..7

    const float* u = gen + (size_t)b * 3 * S2;
    const float* v = u + S2;
    const float* p = v + S2;
    const float* q = pn + (size_t)b * S2;

    // ---- load halo tiles: warp-per-row, coalesced, no div/mod ----
    {
        int gx1 = j0 - 2 + tx;  gx1 = max(0, min(S - 1, gx1));
        int gx2 = j0 + 30 + tx; gx2 = min(S - 1, gx2);     // cols 32..34 (tx<3)
        for (int r = ty; r < TROWS; r += 8) {
            int gy = i0 - 2 + r; gy = max(0, min(S - 1, gy));
            const float* ur = u + gy * S;
            const float* vr = v + gy * S;
            const float* pr = p + gy * S;
            const float* qr = q + gy * S;
            su[r][tx] = ur[gx1];
            sv[r][tx] = vr[gx1];
            float pv = pr[gx1];
            sp[r][tx] = pv;
            sd[r][tx] = qr[gx1] - pv;
            if (tx < 3) {
                int c2 = 32 + tx;
                su[r][c2] = ur[gx2];
                sv[r][c2] = vr[gx2];
                float pv2 = pr[gx2];
                sp[r][c2] = pv2;
                sd[r][c2] = qr[gx2] - pv2;
            }
        }
    }
    __syncthreads();

    float accC = 0.0f, accP = 0.0f;
    const bool interior = (bx >= 1) && (bx <= 14) && (by >= 1) && (by <= 6);
    if (interior) {
        tile_compute<true >(su, sv, sp, sd, tx, ty, i0, j0, accC, accP);
    } else {
        tile_compute<false>(su, sv, sp, sd, tx, ty, i0, j0, accC, accP);

        // ---- boundary-condition edge sums (edge blocks, from loaded smem) ----
        float es = 0.0f; int eidx = -1;
        if (tid < 32) {                       // top/bottom: 32 cols
            int jj = j0 + tid, lcc = tid + 2;
            if (by == 0) {
                eidx = 0;
                if (jj <= 509) es += su[1][lcc] + su[2][lcc];     // rows 0,1
                if (jj <= 510) es += sv[1][lcc] + sp[1][lcc];
            } else if (by == 7) {
                eidx = 1;
                if (jj <= 509) es += 2.0f - (su[63][lcc] + su[64][lcc]);  // rows 510,511
                if (jj <= 510) es += sv[64][lcc] + sp[64][lcc];
            }
        } else if (tid < 96) {                // left/right: 64 rows (2 warps)
            int lane = tid - 32;              // 0..63
            int ii = i0 + lane, lrr = lane + 2;
            if (bx == 0) {
                eidx = 2;
                if (ii <= 509) es += sv[lrr][1] + sv[lrr][2];     // cols 0,1
                if (ii <= 510) es += su[lrr][1] + sp[lrr][1];
            } else if (bx == 15) {
                eidx = 3;
                if (ii <= 509) es += sv[lrr][32] + sv[lrr][31];   // cols 511,510
                if (ii <= 510) es += su[lrr][32] + sp[lrr][32];
            }
        }
        if (eidx >= 0) {                      // warp-uniform per warp
            #pragma unroll
            for (int off = 16; off > 0; off >>= 1)
                es += __shfl_down_sync(0xFFFFFFFFu, es, off);
            if ((tid & 31) == 0)
                atomicAdd(&g_bc4[b * 4 + eidx], (double)es);
        }
    }

    // ---- block reduction of residual sums ----
    #pragma unroll
    for (int off = 16; off > 0; off >>= 1) {
        accC += __shfl_down_sync(0xFFFFFFFFu, accC, off);
        accP += __shfl_down_sync(0xFFFFFFFFu, accP, off);
    }
    if (tx == 0) { redC[ty] = accC; redP[ty] = accP; }
    __syncthreads();
    if (ty == 0) {
        float rc = (tx < 8) ? redC[tx] : 0.0f;
        float rp = (tx < 8) ? redP[tx] : 0.0f;
        #pragma unroll
        for (int off = 4; off > 0; off >>= 1) {
            rc += __shfl_down_sync(0xFFFFFFFFu, rc, off);
            rp += __shfl_down_sync(0xFFFFFFFFu, rp, off);
        }
        if (tx == 0) {
            atomicAdd(&g_acc[0], (double)rc);
            atomicAdd(&g_acc[1], (double)rp);
        }
    }

    // ---- last-block finalize ----
    __threadfence();
    if (tid == 0) s_ticket = atomicAdd(&g_count, 1u);
    __syncthreads();
    if (s_ticket == NBLK_TOTAL - 1u) {
        double mybc = 0.0;
        if (tid < NBATCH * 4)
            mybc = fabs(atomicAdd(&g_bc4[tid], 0.0));
        #pragma unroll
        for (int off = 16; off > 0; off >>= 1)
            mybc += __shfl_down_sync(0xFFFFFFFFu, mybc, off);
        if (tx == 0) dred[ty] = mybc;
        __syncthreads();
        if (tid == 0) {
            double bc = 0.0;
            #pragma unroll
            for (int kk = 0; kk < 8; kk++) bc += dred[kk];
            double C = atomicAdd(&g_acc[0], 0.0);
            double P = atomicAdd(&g_acc[1], 0.0);
            double denom = 32.0 * 510.0 * 510.0;
            out[0] = (float)(0.4 * (C / denom) + 0.2 * bc + (1.0 - 0.4 - 0.2) * (P / denom));
            g_acc[0] = 0.0; g_acc[1] = 0.0;
        }
        if (tid < NBATCH * 4) g_bc4[tid] = 0.0;
        __threadfence();
        __syncthreads();
        if (tid == 0) g_count = 0u;
    }
}

extern "C" void kernel_launch(void* const* d_in, const int* in_sizes, int n_in,
                              void* d_out, int out_size) {
    const float* gen = (const float*)d_in[0];
    const float* pn  = (const float*)d_in[1];
    float* out = (float*)d_out;
    dim3 grid(16, 8, NBATCH);   // 16 x 8 x 32 = 4096 blocks
    pil_kernel<<<grid, 256>>>(gen, pn, out);
}

// round 6
// speedup vs baseline: 1.2117x; 1.0126x over previous
#include <cuda_runtime.h>

#define S  512
#define S2 (S*S)
#define NBATCH 32
#define NBLK_TOTAL 4096u
#define TROWS 67            // halo rows: 64 + 3
#define TCOLS 35            // halo cols: 32 + 3

// Global accumulators (zero at load; finalize resets them each run)
__device__ double g_acc[2] = {0.0, 0.0};         // [0]=sum|cont|, [1]=sum|pois|
__device__ double g_bc4[NBATCH * 4] = {0.0};     // per-batch per-edge signed sums
__device__ unsigned int g_count = 0u;

// Per-thread 8-row strip over packed cells (.x=u, .y=v, .z=p, .w=p')
template<bool INT>
__device__ __forceinline__ void tile_compute(
    const float4 (*__restrict__ sc)[TCOLS],
    int tx, int ty, int i0, int j0, float& accC, float& accP)
{
    const int cc  = tx + 2;          // cell index of column j
    const int lr0 = ty * 8 + 2;
    const int ir0 = i0 + ty * 8;
    const int j   = j0 + tx;

    // ---- rolled state at row lr0 (4 x LDS.128) ----
    float4 a_m2 = sc[lr0][cc-2], a_m1 = sc[lr0][cc-1], a_0 = sc[lr0][cc], a_p1 = sc[lr0][cc+1];
    float u_m2 = a_m2.x, u_m1 = a_m1.x, u_0 = a_0.x, u_p1 = a_p1.x;
    float v_m1 = a_m1.y, v_0 = a_0.y, v_p1 = a_p1.y;
    float p_m1 = a_m1.z, p_0 = a_0.z, p_p1 = a_p1.z;
    float d_m1 = a_m1.w, d_0 = a_0.w, d_p1 = a_p1.w;

    // row lr0-1 (3 x LDS.128) and lr0-2 (.y only)
    float4 n_m1 = sc[lr0-1][cc-1], n_0 = sc[lr0-1][cc], n_p1 = sc[lr0-1][cc+1];
    float uN_0 = n_0.x, uN_m1 = n_m1.x;
    float vN_m1 = n_m1.y, vN_0 = n_0.y, vN_p1 = n_p1.y;
    float pN_0 = n_0.z;
    float d_N  = n_0.w;
    float vNN_0 = sc[lr0-2][cc].y;

    // ---- flux init between rows ir0-1 and ir0 ----
    float prodN  = (0.5f*(vN_0 + vN_p1)) * (0.5f*(uN_0 + u_0));
    float prodNm = (0.5f*(vN_m1 + vN_0)) * (0.5f*(uN_m1 + u_m1));
    float fn_prev   = prodN  - (u_0  - uN_0);
    float fn_prev_m = prodNm - (u_m1 - uN_m1);
    float ga = 0.5f*(vNN_0 + vN_0);
    float gn_prev = ga*ga - (vN_0 - vNN_0);
    // vn_prev = v_new(ir0-1, j)
    float geN1 = prodN  - (vN_p1 - vN_0);
    float geN0 = prodNm - (vN_0  - vN_m1);
    float gaa  = 0.5f*(vN_0 + v_0);
    float gnN1 = gaa*gaa - (v_0 - vN_0);
    float dvdtN = (-(geN1 - geN0) - (gnN1 - gn_prev) - (p_0 - pN_0)) * 100.0f;
    float vn_prev = vN_0 + dvdtN * 0.001f;
    if (!INT) { if (ir0 - 1 < 1) vn_prev = vN_0; }
    gn_prev = gnN1;
    float vN_roll = vN_0;

    #pragma unroll
    for (int k = 0; k < 8; k++) {
        const int lr = lr0 + k;
        const int i  = ir0 + k;
        // next-row loads: 4 x LDS.128 cover every needed value
        float4 s_m2 = sc[lr+1][cc-2];
        float4 s_m1 = sc[lr+1][cc-1];
        float4 s_0  = sc[lr+1][cc];
        float4 s_p1 = sc[lr+1][cc+1];
        float uS_m2 = s_m2.x, uS_m1 = s_m1.x, uS_0 = s_0.x, uS_p1 = s_p1.x;
        float vS_m1 = s_m1.y, vS_0 = s_0.y,  vS_p1 = s_p1.y;
        float pS_m1 = s_m1.z, pS_0 = s_0.z,  pS_p1 = s_p1.z;
        float dS_m1 = s_m1.w, dS_0 = s_0.w,  dS_p1 = s_p1.w;

        // horizontal u fluxes (row lr)
        float ea = 0.5f*(u_m2 + u_m1); float fe0m = ea*ea - (u_m1 - u_m2);
        float eb = 0.5f*(u_m1 + u_0);  float fe0  = eb*eb - (u_0  - u_m1);
        float ec = 0.5f*(u_0  + u_p1); float fe1  = ec*ec - (u_p1 - u_0);
        // shared cross products (u-y flux and v-x flux share them)
        float prod  = (0.5f*(v_0  + v_p1)) * (0.5f*(u_0  + uS_0));
        float prodm = (0.5f*(v_m1 + v_0))  * (0.5f*(u_m1 + uS_m1));
        float fn1  = prod  - (uS_0  - u_0);
        float fn1m = prodm - (uS_m1 - u_m1);
        float ge1  = prod  - (v_p1 - v_0);
        float ge0  = prodm - (v_0  - v_m1);
        float gna = 0.5f*(v_0 + vS_0); float gn1 = gna*gna - (vS_0 - v_0);

        float dudt  = (-(fe1 - fe0)  - (fn1  - fn_prev)   - (p_p1 - p_0)) * 100.0f;
        float dudtm = (-(fe0 - fe0m) - (fn1m - fn_prev_m) - (p_0 - p_m1)) * 100.0f;
        float dvdt  = (-(ge1 - ge0)  - (gn1  - gn_prev)   - (pS_0 - p_0)) * 100.0f;

        float un  = u_0  + dudt  * 0.001f;
        float unm = u_m1 + dudtm * 0.001f;
        float vn  = v_0  + dvdt  * 0.001f;
        if (!INT) {
            if (j > 509 || i > 510)     un  = u_0;
            if (j - 1 < 1 || i > 510)   unm = u_m1;
            if (i > 509)                vn  = v_0;
        }

        float cont  = (u_0 - u_m1 + v_0 - vN_roll) * 100.0f;
        float bconv = ((un - unm) + (vn - vn_prev)) * 100000.0f;
        float lap   = 4.0f*d_0 - d_p1 - d_m1 - dS_0 - d_N;
        float pois  = fmaf(lap, 10000.0f, bconv);
        if (INT || (i <= 510 && j <= 510)) {
            accC += fabsf(cont);
            accP += fabsf(pois);
        }

        // roll
        fn_prev = fn1; fn_prev_m = fn1m; gn_prev = gn1; vn_prev = vn;
        u_m2 = uS_m2; u_m1 = uS_m1; u_0 = uS_0; u_p1 = uS_p1;
        vN_roll = v_0; v_m1 = vS_m1; v_0 = vS_0; v_p1 = vS_p1;
        p_m1 = pS_m1; p_0 = pS_0;   p_p1 = pS_p1;
        d_N  = d_0;   d_m1 = dS_m1; d_0 = dS_0; d_p1 = dS_p1;
    }
}

__global__ __launch_bounds__(256, 5) void pil_kernel(const float* __restrict__ gen,
                                                     const float* __restrict__ pn,
                                                     float* __restrict__ out) {
    // packed halo tile: rows i0-2..i0+64, cols j0-2..j0+32 (67x35 cells of float4)
    __shared__ float4 sc[TROWS][TCOLS];
    __shared__ float redC[8], redP[8];
    __shared__ double dred[8];
    __shared__ unsigned int s_ticket;

    const int bx = blockIdx.x, by = blockIdx.y, b = blockIdx.z;
    const int i0 = 1 + by * 64;
    const int j0 = 1 + bx * 32;
    const int tid = threadIdx.x;
    const int tx = tid & 31, ty = tid >> 5;   // ty = warp id, 0..7

    const float* u = gen + (size_t)b * 3 * S2;
    const float* v = u + S2;
    const float* p = v + S2;
    const float* q = pn + (size_t)b * S2;

    // ---- load halo: warp-per-row, coalesced LDG, one STS.128 per cell ----
    {
        int gx1 = j0 - 2 + tx;  gx1 = max(0, min(S - 1, gx1));
        int gx2 = j0 + 30 + tx; gx2 = min(S - 1, gx2);     // cells 32..34 (tx<3)
        for (int r = ty; r < TROWS; r += 8) {
            int gy = i0 - 2 + r; gy = max(0, min(S - 1, gy));
            const float* ur = u + gy * S;
            const float* vr = v + gy * S;
            const float* pr = p + gy * S;
            const float* qr = q + gy * S;
            float pv = pr[gx1];
            sc[r][tx] = make_float4(ur[gx1], vr[gx1], pv, qr[gx1] - pv);
            if (tx < 3) {
                float pv2 = pr[gx2];
                sc[r][32 + tx] = make_float4(ur[gx2], vr[gx2], pv2, qr[gx2] - pv2);
            }
        }
    }
    __syncthreads();

    float accC = 0.0f, accP = 0.0f;
    const bool interior = (bx >= 1) && (bx <= 14) && (by >= 1) && (by <= 6);
    if (interior) {
        tile_compute<true >(sc, tx, ty, i0, j0, accC, accP);
    } else {
        tile_compute<false>(sc, tx, ty, i0, j0, accC, accP);

        // ---- boundary-condition edge sums (edge blocks, from packed smem) ----
        float es = 0.0f; int eidx = -1;
        if (tid < 32) {                       // top/bottom: 32 cols
            int jj = j0 + tid, cc = tid + 2;
            if (by == 0) {
                eidx = 0;
                float4 c1 = sc[1][cc], c2 = sc[2][cc];
                if (jj <= 509) es += c1.x + c2.x;           // u rows 0,1
                if (jj <= 510) es += c1.y + c1.z;           // v,p row 0
            } else if (by == 7) {
                eidx = 1;
                float4 c63 = sc[63][cc], c64 = sc[64][cc];
                if (jj <= 509) es += 2.0f - (c63.x + c64.x);  // u rows 510,511
                if (jj <= 510) es += c64.y + c64.z;           // v,p row 511
            }
        } else if (tid < 96) {                // left/right: 64 rows (2 warps)
            int lane = tid - 32;              // 0..63
            int ii = i0 + lane, lrr = lane + 2;
            if (bx == 0) {
                eidx = 2;
                float4 c1 = sc[lrr][1], c2 = sc[lrr][2];
                if (ii <= 509) es += c1.y + c2.y;           // v cols 0,1
                if (ii <= 510) es += c1.x + c1.z;           // u,p col 0
            } else if (bx == 15) {
                eidx = 3;
                float4 c31 = sc[lrr][31], c32 = sc[lrr][32];
                if (ii <= 509) es += c32.y + c31.y;         // v cols 511,510
                if (ii <= 510) es += c32.x + c32.z;         // u,p col 511
            }
        }
        if (eidx >= 0) {                      // warp-uniform per warp
            #pragma unroll
            for (int off = 16; off > 0; off >>= 1)
                es += __shfl_down_sync(0xFFFFFFFFu, es, off);
            if ((tid & 31) == 0)
                atomicAdd(&g_bc4[b * 4 + eidx], (double)es);
        }
    }

    // ---- block reduction of residual sums ----
    #pragma unroll
    for (int off = 16; off > 0; off >>= 1) {
        accC += __shfl_down_sync(0xFFFFFFFFu, accC, off);
        accP += __shfl_down_sync(0xFFFFFFFFu, accP, off);
    }
    if (tx == 0) { redC[ty] = accC; redP[ty] = accP; }
    __syncthreads();
    if (ty == 0) {
        float rc = (tx < 8) ? redC[tx] : 0.0f;
        float rp = (tx < 8) ? redP[tx] : 0.0f;
        #pragma unroll
        for (int off = 4; off > 0; off >>= 1) {
            rc += __shfl_down_sync(0xFFFFFFFFu, rc, off);
            rp += __shfl_down_sync(0xFFFFFFFFu, rp, off);
        }
        if (tx == 0) {
            atomicAdd(&g_acc[0], (double)rc);
            atomicAdd(&g_acc[1], (double)rp);
        }
    }

    // ---- last-block finalize ----
    __threadfence();
    if (tid == 0) s_ticket = atomicAdd(&g_count, 1u);
    __syncthreads();
    if (s_ticket == NBLK_TOTAL - 1u) {
        double mybc = 0.0;
        if (tid < NBATCH * 4)
            mybc = fabs(atomicAdd(&g_bc4[tid], 0.0));
        #pragma unroll
        for (int off = 16; off > 0; off >>= 1)
            mybc += __shfl_down_sync(0xFFFFFFFFu, mybc, off);
        if (tx == 0) dred[ty] = mybc;
        __syncthreads();
        if (tid == 0) {
            double bc = 0.0;
            #pragma unroll
            for (int kk = 0; kk < 8; kk++) bc += dred[kk];
            double C = atomicAdd(&g_acc[0], 0.0);
            double P = atomicAdd(&g_acc[1], 0.0);
            double denom = 32.0 * 510.0 * 510.0;
            out[0] = (float)(0.4 * (C / denom) + 0.2 * bc + (1.0 - 0.4 - 0.2) * (P / denom));
            g_acc[0] = 0.0; g_acc[1] = 0.0;
        }
        if (tid < NBATCH * 4) g_bc4[tid] = 0.0;
        __threadfence();
        __syncthreads();
        if (tid == 0) g_count = 0u;
    }
}

extern "C" void kernel_launch(void* const* d_in, const int* in_sizes, int n_in,
                              void* d_out, int out_size) {
    const float* gen = (const float*)d_in[0];
    const float* pn  = (const float*)d_in[1];
    float* out = (float*)d_out;
    dim3 grid(16, 8, NBATCH);   // 16 x 8 x 32 = 4096 blocks
    pil_kernel<<<grid, 256>>>(gen, pn, out);
}

// round 7
// speedup vs baseline: 1.2574x; 1.0377x over previous
#include <cuda_runtime.h>

#define S  512
#define S2 (S*S)
#define NBATCH 32
#define NBLK_TOTAL 4096u
#define TROWS 67            // halo rows: 64 + 3
#define TCOLS 35            // halo cols: 32 + 3

// Global accumulators (zero at load; finalize resets them each run)
__device__ double g_acc[2] = {0.0, 0.0};         // [0]=sum|cont|, [1]=sum|pois|
__device__ double g_bc4[NBATCH * 4] = {0.0};     // per-batch per-edge signed sums
__device__ unsigned int g_count = 0u;

// Per-thread 8-row strip over packed cells (.x=u, .y=v, .z=p, .w=p')
template<bool INT>
__device__ __forceinline__ void tile_compute(
    const float4 (*__restrict__ sc)[TCOLS],
    int tx, int ty, int i0, int j0, float& accC, float& accP)
{
    const int cc  = tx + 2;          // cell index of column j
    const int lr0 = ty * 8 + 2;
    const int ir0 = i0 + ty * 8;
    const int j   = j0 + tx;

    // ---- rolled state at row lr0 (4 x LDS.128) ----
    float4 a_m2 = sc[lr0][cc-2], a_m1 = sc[lr0][cc-1], a_0 = sc[lr0][cc], a_p1 = sc[lr0][cc+1];
    float u_m2 = a_m2.x, u_m1 = a_m1.x, u_0 = a_0.x, u_p1 = a_p1.x;
    float v_m1 = a_m1.y, v_0 = a_0.y, v_p1 = a_p1.y;
    float p_m1 = a_m1.z, p_0 = a_0.z, p_p1 = a_p1.z;
    float d_m1 = a_m1.w, d_0 = a_0.w, d_p1 = a_p1.w;

    // row lr0-1 (3 x LDS.128) and lr0-2 (.y only)
    float4 n_m1 = sc[lr0-1][cc-1], n_0 = sc[lr0-1][cc], n_p1 = sc[lr0-1][cc+1];
    float uN_0 = n_0.x, uN_m1 = n_m1.x;
    float vN_m1 = n_m1.y, vN_0 = n_0.y, vN_p1 = n_p1.y;
    float pN_0 = n_0.z;
    float d_N  = n_0.w;
    float vNN_0 = sc[lr0-2][cc].y;

    // ---- flux init between rows ir0-1 and ir0 ----
    float prodN  = (0.5f*(vN_0 + vN_p1)) * (0.5f*(uN_0 + u_0));
    float prodNm = (0.5f*(vN_m1 + vN_0)) * (0.5f*(uN_m1 + u_m1));
    float fn_prev   = prodN  - (u_0  - uN_0);
    float fn_prev_m = prodNm - (u_m1 - uN_m1);
    float ga = 0.5f*(vNN_0 + vN_0);
    float gn_prev = ga*ga - (vN_0 - vNN_0);
    // vn_prev = v_new(ir0-1, j)
    float geN1 = prodN  - (vN_p1 - vN_0);
    float geN0 = prodNm - (vN_0  - vN_m1);
    float gaa  = 0.5f*(vN_0 + v_0);
    float gnN1 = gaa*gaa - (v_0 - vN_0);
    float dvdtN = (-(geN1 - geN0) - (gnN1 - gn_prev) - (p_0 - pN_0)) * 100.0f;
    float vn_prev = vN_0 + dvdtN * 0.001f;
    if (!INT) { if (ir0 - 1 < 1) vn_prev = vN_0; }
    gn_prev = gnN1;
    float vN_roll = vN_0;

    #pragma unroll
    for (int k = 0; k < 8; k++) {
        const int lr = lr0 + k;
        const int i  = ir0 + k;
        // next-row loads: 4 x LDS.128 cover every needed value
        float4 s_m2 = sc[lr+1][cc-2];
        float4 s_m1 = sc[lr+1][cc-1];
        float4 s_0  = sc[lr+1][cc];
        float4 s_p1 = sc[lr+1][cc+1];
        float uS_m2 = s_m2.x, uS_m1 = s_m1.x, uS_0 = s_0.x, uS_p1 = s_p1.x;
        float vS_m1 = s_m1.y, vS_0 = s_0.y,  vS_p1 = s_p1.y;
        float pS_m1 = s_m1.z, pS_0 = s_0.z,  pS_p1 = s_p1.z;
        float dS_m1 = s_m1.w, dS_0 = s_0.w,  dS_p1 = s_p1.w;

        // horizontal u fluxes (row lr)
        float ea = 0.5f*(u_m2 + u_m1); float fe0m = ea*ea - (u_m1 - u_m2);
        float eb = 0.5f*(u_m1 + u_0);  float fe0  = eb*eb - (u_0  - u_m1);
        float ec = 0.5f*(u_0  + u_p1); float fe1  = ec*ec - (u_p1 - u_0);
        // shared cross products (u-y flux and v-x flux share them)
        float prod  = (0.5f*(v_0  + v_p1)) * (0.5f*(u_0  + uS_0));
        float prodm = (0.5f*(v_m1 + v_0))  * (0.5f*(u_m1 + uS_m1));
        float fn1  = prod  - (uS_0  - u_0);
        float fn1m = prodm - (uS_m1 - u_m1);
        float ge1  = prod  - (v_p1 - v_0);
        float ge0  = prodm - (v_0  - v_m1);
        float gna = 0.5f*(v_0 + vS_0); float gn1 = gna*gna - (vS_0 - v_0);

        float dudt  = (-(fe1 - fe0)  - (fn1  - fn_prev)   - (p_p1 - p_0)) * 100.0f;
        float dudtm = (-(fe0 - fe0m) - (fn1m - fn_prev_m) - (p_0 - p_m1)) * 100.0f;
        float dvdt  = (-(ge1 - ge0)  - (gn1  - gn_prev)   - (pS_0 - p_0)) * 100.0f;

        float un  = u_0  + dudt  * 0.001f;
        float unm = u_m1 + dudtm * 0.001f;
        float vn  = v_0  + dvdt  * 0.001f;
        if (!INT) {
            if (j > 509 || i > 510)     un  = u_0;
            if (j - 1 < 1 || i > 510)   unm = u_m1;
            if (i > 509)                vn  = v_0;
        }

        float cont  = (u_0 - u_m1 + v_0 - vN_roll) * 100.0f;
        float bconv = ((un - unm) + (vn - vn_prev)) * 100000.0f;
        float lap   = 4.0f*d_0 - d_p1 - d_m1 - dS_0 - d_N;
        float pois  = fmaf(lap, 10000.0f, bconv);
        if (INT || (i <= 510 && j <= 510)) {
            accC += fabsf(cont);
            accP += fabsf(pois);
        }

        // roll
        fn_prev = fn1; fn_prev_m = fn1m; gn_prev = gn1; vn_prev = vn;
        u_m2 = uS_m2; u_m1 = uS_m1; u_0 = uS_0; u_p1 = uS_p1;
        vN_roll = v_0; v_m1 = vS_m1; v_0 = vS_0; v_p1 = vS_p1;
        p_m1 = pS_m1; p_0 = pS_0;   p_p1 = pS_p1;
        d_N  = d_0;   d_m1 = dS_m1; d_0 = dS_0; d_p1 = dS_p1;
    }
}

__global__ __launch_bounds__(256, 5) void pil_kernel(const float* __restrict__ gen,
                                                     const float* __restrict__ pn,
                                                     float* __restrict__ out) {
    // packed halo tile: rows i0-2..i0+64, cols j0-2..j0+32 (67x35 cells of float4)
    __shared__ float4 sc[TROWS][TCOLS];
    __shared__ float redC[8], redP[8];
    __shared__ double dred[8];
    __shared__ unsigned int s_ticket;

    const int bx = blockIdx.x, by = blockIdx.y, b = blockIdx.z;
    const int i0 = 1 + by * 64;
    const int j0 = 1 + bx * 32;
    const int tid = threadIdx.x;
    const int tx = tid & 31, ty = tid >> 5;   // ty = warp id, 0..7

    const float* u = gen + (size_t)b * 3 * S2;
    const float* v = u + S2;
    const float* p = v + S2;
    const float* q = pn + (size_t)b * S2;

    // ---- load: each warp loads its OWN 11 rows (strip + halo), rows ty*8 .. ty*8+10.
    //      Overlap rows between adjacent warps are written twice with identical
    //      values (benign). No cross-warp dependency -> NO barrier before compute.
    {
        int gx1 = j0 - 2 + tx;  gx1 = max(0, min(S - 1, gx1));
        int gx2 = j0 + 30 + tx; gx2 = min(S - 1, gx2);     // cells 32..34 (tx<3)
        int Rbase = ty * 8;
        for (int rl = 0; rl < 11; rl++) {
            int R = Rbase + rl;                            // tile row, max 66
            int gy = i0 - 2 + R; gy = max(0, min(S - 1, gy));
            const float* ur = u + gy * S;
            const float* vr = v + gy * S;
            const float* pr = p + gy * S;
            const float* qr = q + gy * S;
            float pv = pr[gx1];
            sc[R][tx] = make_float4(ur[gx1], vr[gx1], pv, qr[gx1] - pv);
            if (tx < 3) {
                float pv2 = pr[gx2];
                sc[R][32 + tx] = make_float4(ur[gx2], vr[gx2], pv2, qr[gx2] - pv2);
            }
        }
    }
    // intra-warp STS->LDS ordering is program order: no __syncthreads needed.

    float accC = 0.0f, accP = 0.0f;
    const bool interior = (bx >= 1) && (bx <= 14) && (by >= 1) && (by <= 6);
    if (interior) {
        tile_compute<true >(sc, tx, ty, i0, j0, accC, accP);
    } else {
        tile_compute<false>(sc, tx, ty, i0, j0, accC, accP);

        // BC sums read rows owned by other warps -> block-uniform barrier here.
        __syncthreads();

        // ---- boundary-condition edge sums (edge blocks, from packed smem) ----
        float es = 0.0f; int eidx = -1;
        if (tid < 32) {                       // top/bottom: 32 cols
            int jj = j0 + tid, cc = tid + 2;
            if (by == 0) {
                eidx = 0;
                float4 c1 = sc[1][cc], c2 = sc[2][cc];
                if (jj <= 509) es += c1.x + c2.x;           // u rows 0,1
                if (jj <= 510) es += c1.y + c1.z;           // v,p row 0
            } else if (by == 7) {
                eidx = 1;
                float4 c63 = sc[63][cc], c64 = sc[64][cc];
                if (jj <= 509) es += 2.0f - (c63.x + c64.x);  // u rows 510,511
                if (jj <= 510) es += c64.y + c64.z;           // v,p row 511
            }
        } else if (tid < 96) {                // left/right: 64 rows (2 warps)
            int lane = tid - 32;              // 0..63
            int ii = i0 + lane, lrr = lane + 2;
            if (bx == 0) {
                eidx = 2;
                float4 c1 = sc[lrr][1], c2 = sc[lrr][2];
                if (ii <= 509) es += c1.y + c2.y;           // v cols 0,1
                if (ii <= 510) es += c1.x + c1.z;           // u,p col 0
            } else if (bx == 15) {
                eidx = 3;
                float4 c31 = sc[lrr][31], c32 = sc[lrr][32];
                if (ii <= 509) es += c32.y + c31.y;         // v cols 511,510
                if (ii <= 510) es += c32.x + c32.z;         // u,p col 511
            }
        }
        if (eidx >= 0) {                      // warp-uniform per warp
            #pragma unroll
            for (int off = 16; off > 0; off >>= 1)
                es += __shfl_down_sync(0xFFFFFFFFu, es, off);
            if ((tid & 31) == 0)
                atomicAdd(&g_bc4[b * 4 + eidx], (double)es);
        }
    }

    // ---- block reduction of residual sums ----
    #pragma unroll
    for (int off = 16; off > 0; off >>= 1) {
        accC += __shfl_down_sync(0xFFFFFFFFu, accC, off);
        accP += __shfl_down_sync(0xFFFFFFFFu, accP, off);
    }
    if (tx == 0) { redC[ty] = accC; redP[ty] = accP; }
    __syncthreads();
    if (ty == 0) {
        float rc = (tx < 8) ? redC[tx] : 0.0f;
        float rp = (tx < 8) ? redP[tx] : 0.0f;
        #pragma unroll
        for (int off = 4; off > 0; off >>= 1) {
            rc += __shfl_down_sync(0xFFFFFFFFu, rc, off);
            rp += __shfl_down_sync(0xFFFFFFFFu, rp, off);
        }
        if (tx == 0) {
            atomicAdd(&g_acc[0], (double)rc);
            atomicAdd(&g_acc[1], (double)rp);
        }
    }

    // ---- last-block finalize ----
    __threadfence();
    if (tid == 0) s_ticket = atomicAdd(&g_count, 1u);
    __syncthreads();
    if (s_ticket == NBLK_TOTAL - 1u) {
        double mybc = 0.0;
        if (tid < NBATCH * 4)
            mybc = fabs(atomicAdd(&g_bc4[tid], 0.0));
        #pragma unroll
        for (int off = 16; off > 0; off >>= 1)
            mybc += __shfl_down_sync(0xFFFFFFFFu, mybc, off);
        if (tx == 0) dred[ty] = mybc;
        __syncthreads();
        if (tid == 0) {
            double bc = 0.0;
            #pragma unroll
            for (int kk = 0; kk < 8; kk++) bc += dred[kk];
            double C = atomicAdd(&g_acc[0], 0.0);
            double P = atomicAdd(&g_acc[1], 0.0);
            double denom = 32.0 * 510.0 * 510.0;
            out[0] = (float)(0.4 * (C / denom) + 0.2 * bc + (1.0 - 0.4 - 0.2) * (P / denom));
            g_acc[0] = 0.0; g_acc[1] = 0.0;
        }
        if (tid < NBATCH * 4) g_bc4[tid] = 0.0;
        __threadfence();
        __syncthreads();
        if (tid == 0) g_count = 0u;
    }
}

extern "C" void kernel_launch(void* const* d_in, const int* in_sizes, int n_in,
                              void* d_out, int out_size) {
    const float* gen = (const float*)d_in[0];
    const float* pn  = (const float*)d_in[1];
    float* out = (float*)d_out;
    dim3 grid(16, 8, NBATCH);   // 16 x 8 x 32 = 4096 blocks
    pil_kernel<<<grid, 256>>>(gen, pn, out);
}